// round 4
// baseline (speedup 1.0000x reference)
#include <cuda_runtime.h>
#include <cstdint>

// VectorQuantizer: z [32,256,64,64] f32, emb [1024,256] f32
// out = concat( z_q [32,256,64,64] f32 , idx [131072] f32 )
//
// Bit-match the reference's argmin:
//   dist_e = fl( fl(z_sq + e_sq_e) - fl(2*dot_e) ), argmin_e, first-index ties.
// dot: sequential-k FFMA chain (== cublas SGEMM order).
// z_sq/e_sq: warp-per-row, lane-strided (c = lane+32i), UNFUSED mul+add,
//            xor shuffle tree. Verified bit-exact (R3: output0 rel_err = 0).

#define N_TOK   131072
#define KDIM    256
#define NEMB    1024
#define CH_STRIDE 4096            // floats between channels in z / out
#define B_STRIDE  (256*4096)      // floats between batches

#define TM 128    // tokens per CTA
#define TN 128    // codes per e-chunk
#define KC 16     // k-chunk

__device__ float g_esq[NEMB];

// ---------------------------------------------------------------------------
// Kernel 1: esq[e] = sum_c fl(emb[e][c]^2)  (one warp per code, XLA order)
// ---------------------------------------------------------------------------
__global__ void esq_kernel(const float* __restrict__ emb) {
    int warp = (blockIdx.x * blockDim.x + threadIdx.x) >> 5;
    int lane = threadIdx.x & 31;
    if (warp >= NEMB) return;
    const float* row = emb + (size_t)warp * KDIM;
    float s = 0.f;
#pragma unroll
    for (int c = lane; c < KDIM; c += 32) {
        float v = row[c];
        s = __fadd_rn(s, __fmul_rn(v, v));
    }
#pragma unroll
    for (int o = 16; o; o >>= 1)
        s = __fadd_rn(s, __shfl_xor_sync(0xffffffffu, s, o));
    if (lane == 0) g_esq[warp] = s;
}

// ---------------------------------------------------------------------------
// Kernel 2: fused z_sq + GEMM + argmin + gather/scatter
//   grid.x = N_TOK/TM = 1024 CTAs, 256 threads (16x16), 8x8 micro-tile
// ---------------------------------------------------------------------------
__global__ __launch_bounds__(256, 2)
void vq_kernel(const float* __restrict__ z, const float* __restrict__ emb,
               float* __restrict__ out, float* __restrict__ out_idx,
               int write_idx) {
    __shared__ float z_s[KC][TM];          // 8 KB
    __shared__ float e_s[KC][TN];          // 8 KB (emb tile, transposed)
    __shared__ union {
        struct { float m[TM][16]; int idx[TM][16]; } red;   // 16 KB (phase 3)
        float zsq_t[TM][33];                                // 16.9 KB (phase 1)
    } ovl;
    __shared__ float sh_esq[NEMB];         // 4 KB
    __shared__ float sh_zsq[TM];
    __shared__ int   final_idx[TM];

    const int tid = threadIdx.x;
    const int tx  = tid & 15;              // code group
    const int ty  = tid >> 4;              // token group
    const int n0  = blockIdx.x * TM;
    const int b   = n0 >> 12;              // n0 / 4096 (TM=128 divides 4096)
    const int hw0 = n0 & 4095;

    const float* zbase = z + (size_t)b * B_STRIDE + hw0;   // + c*4096 + tok

    for (int i = tid; i < NEMB; i += 256) sh_esq[i] = g_esq[i];

    // ================= phase 1: z_sq in XLA row-reduce order ==============
    {
        const int w = tid >> 5;            // warp 0..7, owns tokens w*16..+15
        const int l = tid & 31;
        float s[16];
#pragma unroll
        for (int t = 0; t < 16; t++) s[t] = 0.f;

        for (int cc = 0; cc < KDIM / 32; cc++) {     // chunks of 32 channels
            __syncthreads();
            // load 32 c x 128 tok transposed into zsq_t[tok][c_local]
#pragma unroll
            for (int r = 0; r < 4; r++) {
                int cl   = r * 8 + w;                 // 0..31
                int tok4 = l * 4;
                float4 v = *(const float4*)(zbase + (size_t)(cc * 32 + cl) * CH_STRIDE + tok4);
                ovl.zsq_t[tok4 + 0][cl] = v.x;
                ovl.zsq_t[tok4 + 1][cl] = v.y;
                ovl.zsq_t[tok4 + 2][cl] = v.z;
                ovl.zsq_t[tok4 + 3][cl] = v.w;
            }
            __syncthreads();
            // lane l accumulates c = cc*32 + l  (ascending cc => c = l + 32i)
#pragma unroll
            for (int t = 0; t < 16; t++) {
                float v = ovl.zsq_t[w * 16 + t][l];
                s[t] = __fadd_rn(s[t], __fmul_rn(v, v));
            }
        }
        // xor tree per token (lane-0 association == shfl_down tree)
#pragma unroll
        for (int t = 0; t < 16; t++) {
            float v = s[t];
#pragma unroll
            for (int o = 16; o; o >>= 1)
                v = __fadd_rn(v, __shfl_xor_sync(0xffffffffu, v, o));
            if (l == 0) sh_zsq[w * 16 + t] = v;
        }
    }
    __syncthreads();

    float zsq_r[8];
#pragma unroll
    for (int i = 0; i < 8; i++) zsq_r[i] = sh_zsq[ty * 8 + i];

    float best[8];
    int   bidx[8];
#pragma unroll
    for (int i = 0; i < 8; i++) { best[i] = 3.0e38f; bidx[i] = 0; }

    // ================= phase 2: GEMM + fold argmin ========================
    for (int e0 = 0; e0 < NEMB; e0 += TN) {
        float acc[8][8];
#pragma unroll
        for (int i = 0; i < 8; i++)
#pragma unroll
            for (int j = 0; j < 8; j++) acc[i][j] = 0.f;

        for (int c0 = 0; c0 < KDIM; c0 += KC) {
            __syncthreads();
            // ---- load z tile: KC x TM floats = 512 float4, 2 per thread ----
#pragma unroll
            for (int r = 0; r < 2; r++) {
                int q   = tid + r * 256;       // float4 id 0..511
                int kk  = q >> 5;              // 0..15
                int col = (q & 31) << 2;       // 0..124
                float4 v = *(const float4*)(zbase + (size_t)(c0 + kk) * CH_STRIDE + col);
                *(float4*)&z_s[kk][col] = v;
            }
            // ---- load emb tile transposed: TN rows x KC floats ----
#pragma unroll
            for (int r = 0; r < 2; r++) {
                int q   = tid + r * 256;       // float4 id 0..511
                int e   = q >> 2;              // 0..127
                int kk4 = (q & 3) << 2;        // 0,4,8,12
                float4 v = *(const float4*)(emb + (size_t)(e0 + e) * KDIM + c0 + kk4);
                e_s[kk4 + 0][e] = v.x;
                e_s[kk4 + 1][e] = v.y;
                e_s[kk4 + 2][e] = v.z;
                e_s[kk4 + 3][e] = v.w;
            }
            __syncthreads();
            // ---- 8x8 micro-tile FFMA over KC (sequential k, fused) ----
#pragma unroll
            for (int kk = 0; kk < KC; kk++) {
                float a0[8], b0[8];
                *(float4*)&a0[0] = *(const float4*)&z_s[kk][ty * 8 + 0];
                *(float4*)&a0[4] = *(const float4*)&z_s[kk][ty * 8 + 4];
                *(float4*)&b0[0] = *(const float4*)&e_s[kk][tx * 8 + 0];
                *(float4*)&b0[4] = *(const float4*)&e_s[kk][tx * 8 + 4];
#pragma unroll
                for (int i = 0; i < 8; i++)
#pragma unroll
                    for (int j = 0; j < 8; j++)
                        acc[i][j] += a0[i] * b0[j];
            }
        }
        // ---- fold this e-chunk into running argmin (reference rounding) ----
        const int ebase = e0 + tx * 8;
#pragma unroll
        for (int j = 0; j < 8; j++) {
            float es = sh_esq[ebase + j];
#pragma unroll
            for (int i = 0; i < 8; i++) {
                float A = __fadd_rn(zsq_r[i], es);
                float d = __fsub_rn(A, __fmul_rn(2.0f, acc[i][j]));
                if (d < best[i]) { best[i] = d; bidx[i] = ebase + j; }
            }
        }
    }

    // ========= phase 3: reduce across tx (16 thr/token), min+lowest idx ====
    __syncthreads();
#pragma unroll
    for (int i = 0; i < 8; i++) {
        ovl.red.m[ty * 8 + i][tx]   = best[i];
        ovl.red.idx[ty * 8 + i][tx] = bidx[i];
    }
    __syncthreads();
    if (tid < TM) {
        float m = ovl.red.m[tid][0];
        int   ix = ovl.red.idx[tid][0];
#pragma unroll
        for (int t = 1; t < 16; t++) {
            float v  = ovl.red.m[tid][t];
            int   vi = ovl.red.idx[tid][t];
            if (v < m || (v == m && vi < ix)) { m = v; ix = vi; }
        }
        final_idx[tid] = ix;
        if (write_idx) out_idx[n0 + tid] = (float)ix;   // harness dtype = f32
    }
    __syncthreads();

    // ========= phase 4: gather emb[idx] and scatter to NCHW ===============
    float* obase = out + (size_t)b * B_STRIDE + hw0;
    const int tok   = tid & 127;
    const int chalf = tid >> 7;            // 0 or 1
    const int myidx = final_idx[tok];
    const float* erow = emb + (size_t)myidx * KDIM;
#pragma unroll 4
    for (int c = chalf; c < KDIM; c += 2) {
        obase[(size_t)c * CH_STRIDE + tok] = erow[c];
    }
}

// ---------------------------------------------------------------------------
extern "C" void kernel_launch(void* const* d_in, const int* in_sizes, int n_in,
                              void* d_out, int out_size) {
    const float* z   = (const float*)d_in[0];
    const float* emb = (const float*)d_in[1];
    float* out = (float*)d_out;

    const int zq_elems = 32 * 256 * 64 * 64;   // 8388608
    int write_idx = (out_size >= zq_elems + N_TOK) ? 1 : 0;

    esq_kernel<<<NEMB * 32 / 256, 256>>>(emb);
    vq_kernel<<<N_TOK / TM, 256>>>(z, emb, out, out + zq_elems, write_idx);
}

// round 6
// speedup vs baseline: 1.7235x; 1.7235x over previous
#include <cuda_runtime.h>
#include <cuda_bf16.h>
#include <cstdint>

// VectorQuantizer: z [32,256,64,64] f32, emb [1024,256] f32
// out = concat( z_q [32,256,64,64] f32 , idx [131072] f32 )
//
// mma.sync (bf16, legacy HMMA path, sm_103-baseline PTX) split-2 3-pass
// ranking with sound margin EPS; exact repair (bit-matching R4-verified
// arithmetic) for tokens with competitors within EPS.

#define N_TOK   131072
#define KDIM    256
#define NEMB    1024
#define CH_STRIDE 4096
#define B_STRIDE  (256*4096)
#define EPS 3e-4f
#define NCAND 8

__device__ float g_esq[NEMB];
__device__ __nv_bfloat16 g_Bh[NEMB * KDIM];   // 512 KB
__device__ __nv_bfloat16 g_Bl[NEMB * KDIM];   // 512 KB
__device__ int           g_idx[N_TOK];
__device__ unsigned char g_candN[N_TOK];
__device__ short         g_cands[N_TOK * NCAND];

// ---- SMEM layout (dynamic) ----
#define SA_H 0          // A hi: 256 k-rows x 128 tok bf16 (swizzled)  64KB
#define SA_L 65536      // A lo                                        64KB
#define SB   131072     // B double buffer: 2 x (hi 16KB + lo 16KB)    64KB
#define SESQ 196608     // esq 4KB
#define SMG  200704     // merge arrays 24.5KB
#define MG_BEST (SMG)
#define MG_IDX  (SMG + 2048)
#define MG_CNT  (SMG + 4096)
#define MG_CD   (SMG + 6144)    // float[512][6]
#define MG_CE   (SMG + 18432)   // short[512][6]
#define SM_TOTAL 225280

__device__ __forceinline__ uint32_t smem_u32(const void* p) {
    uint32_t a;
    asm("{ .reg .u64 t; cvta.to.shared.u64 t, %1; cvt.u32.u64 %0, t; }" : "=r"(a) : "l"(p));
    return a;
}
__device__ __forceinline__ void ldsm4(uint32_t* r, uint32_t a) {
    asm volatile("ldmatrix.sync.aligned.m8n8.x4.shared.b16 {%0,%1,%2,%3}, [%4];"
                 : "=r"(r[0]), "=r"(r[1]), "=r"(r[2]), "=r"(r[3]) : "r"(a));
}
__device__ __forceinline__ void ldsm4t(uint32_t* r, uint32_t a) {
    asm volatile("ldmatrix.sync.aligned.m8n8.x4.trans.shared.b16 {%0,%1,%2,%3}, [%4];"
                 : "=r"(r[0]), "=r"(r[1]), "=r"(r[2]), "=r"(r[3]) : "r"(a));
}
__device__ __forceinline__ void mma16816(float* c, const uint32_t* a, const uint32_t* b) {
    asm volatile("mma.sync.aligned.m16n8k16.row.col.f32.bf16.bf16.f32 "
                 "{%0,%1,%2,%3}, {%4,%5,%6,%7}, {%8,%9}, {%0,%1,%2,%3};"
                 : "+f"(c[0]), "+f"(c[1]), "+f"(c[2]), "+f"(c[3])
                 : "r"(a[0]), "r"(a[1]), "r"(a[2]), "r"(a[3]), "r"(b[0]), "r"(b[1]));
}
#define CP_COMMIT() asm volatile("cp.async.commit_group;" ::: "memory")
#define CP_WAIT1()  asm volatile("cp.async.wait_group 1;" ::: "memory")
#define CP_WAIT0()  asm volatile("cp.async.wait_group 0;" ::: "memory")

// ======================= Kernel: esq (exact, XLA order) ====================
__global__ void esq_kernel(const float* __restrict__ emb) {
    int warp = (blockIdx.x * blockDim.x + threadIdx.x) >> 5;
    int lane = threadIdx.x & 31;
    if (warp >= NEMB) return;
    const float* row = emb + (size_t)warp * KDIM;
    float s = 0.f;
#pragma unroll
    for (int c = lane; c < KDIM; c += 32) {
        float v = row[c];
        s = __fadd_rn(s, __fmul_rn(v, v));
    }
#pragma unroll
    for (int o = 16; o; o >>= 1)
        s = __fadd_rn(s, __shfl_xor_sync(0xffffffffu, s, o));
    if (lane == 0) g_esq[warp] = s;
}

// ======================= Kernel: convert emb -> bf16 hi/lo =================
__global__ void convB_kernel(const float* __restrict__ emb) {
    int i = (blockIdx.x * 256 + threadIdx.x) * 4;
    float4 v = *(const float4*)(emb + i);
    float vv[4] = {v.x, v.y, v.z, v.w};
    unsigned short hs[4], ls[4];
#pragma unroll
    for (int j = 0; j < 4; j++) {
        __nv_bfloat16 h = __float2bfloat16_rn(vv[j]);
        __nv_bfloat16 l = __float2bfloat16_rn(vv[j] - __bfloat162float(h));
        hs[j] = *(unsigned short*)&h;
        ls[j] = *(unsigned short*)&l;
    }
    uint2 ph = make_uint2((uint32_t)hs[0] | ((uint32_t)hs[1] << 16),
                          (uint32_t)hs[2] | ((uint32_t)hs[3] << 16));
    uint2 pl = make_uint2((uint32_t)ls[0] | ((uint32_t)ls[1] << 16),
                          (uint32_t)ls[2] | ((uint32_t)ls[3] << 16));
    *(uint2*)(g_Bh + i) = ph;
    *(uint2*)(g_Bl + i) = pl;
}

// ======================= Kernel: mma.sync GEMM + argmin ====================
__device__ __forceinline__ void issueB(uint32_t smem_base, int cc, int tid) {
#pragma unroll
    for (int j = 0; j < 8; j++) {
        int idx = tid + j * 256;          // 0..2047 16B granules
        int h = idx >> 10;                // 0 hi, 1 lo
        int n = (idx >> 5) & 31;          // row within chunk
        int c = idx & 31;                 // 16B chunk within row
        const char* src = (const char*)(h ? (const void*)g_Bl : (const void*)g_Bh)
                          + (size_t)(cc * 32 + n) * 512 + (size_t)c * 16;
        uint32_t dst = smem_base + SB + (uint32_t)((cc & 1) * 32768 + h * 16384
                     + n * 512 + ((c ^ (n & 7)) << 4));
        asm volatile("cp.async.cg.shared.global [%0], [%1], 16;" :: "r"(dst), "l"(src) : "memory");
    }
    CP_COMMIT();
}

__global__ __launch_bounds__(256, 1)
void mma_kernel(const float* __restrict__ z) {
    extern __shared__ char smem[];
    const uint32_t smem_base = smem_u32(smem);
    const int tid  = threadIdx.x;
    const int lane = tid & 31;
    const int wid  = tid >> 5;
    const int n0   = blockIdx.x * 128;
    const int b    = n0 >> 12;
    const int hw0  = n0 & 4095;
    const float* zbase = z + (size_t)b * B_STRIDE + hw0;

    float* esq_s  = (float*)(smem + SESQ);
    float* mg_best = (float*)(smem + MG_BEST);
    int*   mg_idx  = (int*)(smem + MG_IDX);
    int*   mg_cnt  = (int*)(smem + MG_CNT);
    float* mg_cd   = (float*)(smem + MG_CD);
    short* mg_ce   = (short*)(smem + MG_CE);

    // prefetch first two B chunks
    issueB(smem_base, 0, tid);
    issueB(smem_base, 1, tid);

    for (int i = tid; i < NEMB; i += 256) esq_s[i] = g_esq[i];

    // ---- convert A: z fp32 -> bf16 hi/lo, k-major swizzled smem ----
#pragma unroll 4
    for (int it = 0; it < 32; it++) {
        int q  = tid + it * 256;          // 0..8191 float4s
        int c  = q >> 5;                  // channel (k) 0..255
        int t4 = (q & 31) << 2;           // token base
        float4 v = *(const float4*)(zbase + (size_t)c * CH_STRIDE + t4);
        float vv[4] = {v.x, v.y, v.z, v.w};
#pragma unroll
        for (int j = 0; j < 4; j++) {
            int m = t4 + j;
            __nv_bfloat16 h = __float2bfloat16_rn(vv[j]);
            __nv_bfloat16 l = __float2bfloat16_rn(vv[j] - __bfloat162float(h));
            uint32_t off = (uint32_t)c * 256 + (uint32_t)((((m >> 3) ^ (c & 7)) << 4) | ((m & 7) << 1));
            *(__nv_bfloat16*)(smem + SA_H + off) = h;
            *(__nv_bfloat16*)(smem + SA_L + off) = l;
        }
    }

    // ---- per-lane ldmatrix address bases ----
    const int l7  = lane & 7;
    const int lt1 = (lane >> 3) & 1;
    const int lt2 = (lane >> 4) & 1;
    const int M0  = wid * 16;
    const uint32_t aoff = (uint32_t)(lt2 * 8 + l7) * 256
                        + (uint32_t)((((M0 >> 3) + lt1) ^ l7) << 4);
    const uint32_t addrAh = smem_base + SA_H + aoff;
    const uint32_t addrAl = smem_base + SA_L + aoff;

    const int gID = lane >> 2, tIG = lane & 3;

    float best[2] = {3.0e38f, 3.0e38f};
    int   bid[2]  = {0, 0};
    int   cn[2]   = {0, 0};
    int   ovf[2]  = {0, 0};

    __syncthreads();   // A + esq ready

    for (int ec = 0; ec < 32; ec++) {
        if (ec < 31) { CP_WAIT1(); } else { CP_WAIT0(); }
        __syncthreads();
        const uint32_t bufb = smem_base + SB + (uint32_t)((ec & 1) * 32768);
        // B row bases for this lane (two n-groups x hi/lo)
        const uint32_t brow0 = bufb + (uint32_t)((lt2 * 8 + l7) * 512);        // NG=0
        const uint32_t brow1 = bufb + (uint32_t)(((16 + lt2 * 8 + l7)) * 512); // NG=16

        float acc[4][4];
#pragma unroll
        for (int t = 0; t < 4; t++)
#pragma unroll
            for (int r = 0; r < 4; r++) acc[t][r] = 0.f;

#pragma unroll
        for (int K = 0; K < 256; K += 16) {
            uint32_t ah[4], al[4];
            ldsm4t(ah, addrAh + (uint32_t)K * 256);
            ldsm4t(al, addrAl + (uint32_t)K * 256);
            const uint32_t kchunk = (uint32_t)(K >> 3) + (uint32_t)lt1;
            const uint32_t sw = ((kchunk ^ (uint32_t)l7) << 4);
            uint32_t bh0[4], bh1[4], bl0[4], bl1[4];
            ldsm4(bh0, brow0 + sw);
            ldsm4(bh1, brow1 + sw);
            ldsm4(bl0, brow0 + 16384 + sw);
            ldsm4(bl1, brow1 + 16384 + sw);
            // pass 1: zh * eh
            mma16816(acc[0], ah, &bh0[0]);
            mma16816(acc[1], ah, &bh0[2]);
            mma16816(acc[2], ah, &bh1[0]);
            mma16816(acc[3], ah, &bh1[2]);
            // pass 2: zh * el
            mma16816(acc[0], ah, &bl0[0]);
            mma16816(acc[1], ah, &bl0[2]);
            mma16816(acc[2], ah, &bl1[0]);
            mma16816(acc[3], ah, &bl1[2]);
            // pass 3: zl * eh
            mma16816(acc[0], al, &bh0[0]);
            mma16816(acc[1], al, &bh0[2]);
            mma16816(acc[2], al, &bh1[0]);
            mma16816(acc[3], al, &bh1[2]);
        }

        // ---- fold into running argmin + candidate lists ----
#pragma unroll
        for (int t = 0; t < 4; t++) {
#pragma unroll
            for (int rr = 0; rr < 4; rr++) {
                int e = ec * 32 + t * 8 + (tIG << 1) + (rr & 1);
                int s = rr >> 1;
                float d = __fmaf_rn(-2.0f, acc[t][rr], esq_s[e]);
                if (d < best[s]) { best[s] = d; bid[s] = e; }
                if (d <= best[s] + EPS) {
                    int base = (tid * 2 + s) * 6;
                    if (cn[s] == 6) {              // compact
                        int k2 = 0;
#pragma unroll
                        for (int j = 0; j < 6; j++) {
                            float dv = mg_cd[base + j];
                            short ev = mg_ce[base + j];
                            if (dv <= best[s] + EPS) { mg_cd[base + k2] = dv; mg_ce[base + k2] = ev; k2++; }
                        }
                        cn[s] = k2;
                    }
                    if (cn[s] < 6) { mg_cd[base + cn[s]] = d; mg_ce[base + cn[s]] = (short)e; cn[s]++; }
                    else ovf[s] = 1;
                }
            }
        }
        __syncthreads();
        if (ec < 30) issueB(smem_base, ec + 2, tid);
    }

    // ---- publish per-lane state, merge 4 lanes per token ----
#pragma unroll
    for (int s = 0; s < 2; s++) {
        int slot = tid * 2 + s;
        mg_best[slot] = best[s];
        mg_idx[slot]  = bid[s];
        mg_cnt[slot]  = ovf[s] ? 255 : cn[s];
    }
    __syncthreads();

    if (tid < 128) {
        int t = tid;
        int w = t >> 4, g = t & 7, s = (t >> 3) & 1;
        int Lbase = w * 32 + g * 4;
        float gb = 3.0e38f; int gi = 0;
#pragma unroll
        for (int q = 0; q < 4; q++) {
            int slot = (Lbase + q) * 2 + s;
            float v = mg_best[slot]; int vi = mg_idx[slot];
            if (v < gb || (v == gb && vi < gi)) { gb = v; gi = vi; }
        }
        int cnt = 0, anyovf = 0;
        short list[NCAND];
#pragma unroll
        for (int q = 0; q < 4; q++) {
            int slot = (Lbase + q) * 2 + s;
            int cq = mg_cnt[slot];
            if (cq == 255) { anyovf = 1; continue; }
            for (int j = 0; j < cq; j++) {
                if (mg_cd[slot * 6 + j] <= gb + EPS) {
                    if (cnt < NCAND) list[cnt++] = mg_ce[slot * 6 + j];
                    else anyovf = 1;
                }
            }
        }
        int n = n0 + t;
        g_idx[n] = gi;
        if (anyovf) g_candN[n] = 255;
        else if (cnt >= 2) {
            g_candN[n] = (unsigned char)cnt;
            for (int j = 0; j < cnt; j++) g_cands[(size_t)n * NCAND + j] = list[j];
        } else g_candN[n] = 0;
    }
}

// ======================= Kernel: exact repair ==============================
__global__ void repair_kernel(const float* __restrict__ z, const float* __restrict__ emb) {
    int n = blockIdx.x * blockDim.x + threadIdx.x;
    if (n >= N_TOK) return;
    int cnt = g_candN[n];
    if (cnt == 0) return;
    int b = n >> 12, hw = n & 4095;
    const float* zb = z + (size_t)b * B_STRIDE + hw;
    // z_sq in XLA order (32 lane-partials, xor-tree association)
    float p[32];
#pragma unroll
    for (int i = 0; i < 32; i++) p[i] = 0.f;
#pragma unroll
    for (int c8 = 0; c8 < 8; c8++)
#pragma unroll
        for (int i = 0; i < 32; i++) {
            float v = zb[(size_t)(c8 * 32 + i) * CH_STRIDE];
            p[i] = __fadd_rn(p[i], __fmul_rn(v, v));
        }
#pragma unroll
    for (int off = 16; off; off >>= 1)
#pragma unroll
        for (int i = 0; i < 16; i++)
            if (i < off) p[i] = __fadd_rn(p[i], p[i + off]);
    float zsq = p[0];

    float m = 3.0e38f; int mi = 0;
    int ncand = (cnt == 255) ? NEMB : cnt;
    for (int j = 0; j < ncand; j++) {
        int e = (cnt == 255) ? j : (int)g_cands[(size_t)n * NCAND + j];
        const float* er = emb + (size_t)e * KDIM;
        float acc = 0.f;
#pragma unroll 8
        for (int c = 0; c < KDIM; c++)
            acc = __fmaf_rn(zb[(size_t)c * CH_STRIDE], er[c], acc);
        float A = __fadd_rn(zsq, g_esq[e]);
        float d = __fsub_rn(A, __fmul_rn(2.0f, acc));
        if (d < m || (d == m && e < mi)) { m = d; mi = e; }
    }
    g_idx[n] = mi;
}

// ======================= Kernel: gather/scatter ============================
__global__ __launch_bounds__(256)
void scatter_kernel(const float* __restrict__ emb, float* __restrict__ out,
                    float* __restrict__ out_idx, int write_idx) {
    const int tid = threadIdx.x;
    const int n0 = blockIdx.x * 128;
    const int b = n0 >> 12, hw0 = n0 & 4095;
    float* obase = out + (size_t)b * B_STRIDE + hw0;
    const int tok = tid & 127;
    const int half = tid >> 7;
    const int myidx = g_idx[n0 + tok];
    if (tid < 128 && write_idx) out_idx[n0 + tid] = (float)g_idx[n0 + tid];
    const float* erow = emb + (size_t)myidx * KDIM;
#pragma unroll 4
    for (int c = half; c < KDIM; c += 2)
        obase[(size_t)c * CH_STRIDE + tok] = erow[c];
}

// ---------------------------------------------------------------------------
extern "C" void kernel_launch(void* const* d_in, const int* in_sizes, int n_in,
                              void* d_out, int out_size) {
    const float* z   = (const float*)d_in[0];
    const float* emb = (const float*)d_in[1];
    float* out = (float*)d_out;

    const int zq_elems = 32 * 256 * 64 * 64;
    int write_idx = (out_size >= zq_elems + N_TOK) ? 1 : 0;

    static int configured = 0;
    cudaFuncSetAttribute(mma_kernel, cudaFuncAttributeMaxDynamicSharedMemorySize, SM_TOTAL);
    (void)configured;

    esq_kernel<<<128, 256>>>(emb);
    convB_kernel<<<256, 256>>>(emb);
    mma_kernel<<<N_TOK / 128, 256, SM_TOTAL>>>(z);
    repair_kernel<<<N_TOK / 256, 256>>>(z, emb);
    scatter_kernel<<<N_TOK / 128, 256>>>(emb, out, out + zq_elems, write_idx);
}

// round 8
// speedup vs baseline: 1.7561x; 1.0189x over previous
#include <cuda_runtime.h>
#include <cuda_bf16.h>
#include <cstdint>

// VectorQuantizer: z [32,256,64,64] f32, emb [1024,256] f32
// out = concat( z_q [32,256,64,64] f32 , idx [131072] f32 )
//
// mma.sync (bf16, legacy HMMA path) split-2 3-pass ranking with sound margin
// EPS; exact repair (bit-matching R4-verified arithmetic) for tokens with
// competitors within EPS. R8 = R7 resubmitted (R7 bench was an infra failure):
// A fragments resident in registers (smem-BW relief), STS.128 A-conversion.

#define N_TOK   131072
#define KDIM    256
#define NEMB    1024
#define CH_STRIDE 4096
#define B_STRIDE  (256*4096)
#define EPS 3e-4f
#define NCAND 8

__device__ float g_esq[NEMB];
__device__ __nv_bfloat16 g_Bh[NEMB * KDIM];   // 512 KB
__device__ __nv_bfloat16 g_Bl[NEMB * KDIM];   // 512 KB
__device__ int           g_idx[N_TOK];
__device__ unsigned char g_candN[N_TOK];
__device__ short         g_cands[N_TOK * NCAND];

// ---- SMEM layout (dynamic) ----
#define SA_H 0          // A hi: 256 k-rows x 128 tok bf16 (swizzled)  64KB
#define SA_L 65536      // A lo                                        64KB
#define SB   131072     // B double buffer: 2 x (hi 16KB + lo 16KB)    64KB
#define SESQ 196608     // esq 4KB
#define SMG  200704     // merge arrays 24.5KB
#define MG_BEST (SMG)
#define MG_IDX  (SMG + 2048)
#define MG_CNT  (SMG + 4096)
#define MG_CD   (SMG + 6144)    // float[512][6]
#define MG_CE   (SMG + 18432)   // short[512][6]
#define SM_TOTAL 225280

__device__ __forceinline__ uint32_t smem_u32(const void* p) {
    uint32_t a;
    asm("{ .reg .u64 t; cvta.to.shared.u64 t, %1; cvt.u32.u64 %0, t; }" : "=r"(a) : "l"(p));
    return a;
}
__device__ __forceinline__ void ldsm4(uint32_t* r, uint32_t a) {
    asm volatile("ldmatrix.sync.aligned.m8n8.x4.shared.b16 {%0,%1,%2,%3}, [%4];"
                 : "=r"(r[0]), "=r"(r[1]), "=r"(r[2]), "=r"(r[3]) : "r"(a));
}
__device__ __forceinline__ void ldsm4t(uint32_t* r, uint32_t a) {
    asm volatile("ldmatrix.sync.aligned.m8n8.x4.trans.shared.b16 {%0,%1,%2,%3}, [%4];"
                 : "=r"(r[0]), "=r"(r[1]), "=r"(r[2]), "=r"(r[3]) : "r"(a));
}
__device__ __forceinline__ void mma16816(float* c, const uint32_t* a, const uint32_t* b) {
    asm volatile("mma.sync.aligned.m16n8k16.row.col.f32.bf16.bf16.f32 "
                 "{%0,%1,%2,%3}, {%4,%5,%6,%7}, {%8,%9}, {%0,%1,%2,%3};"
                 : "+f"(c[0]), "+f"(c[1]), "+f"(c[2]), "+f"(c[3])
                 : "r"(a[0]), "r"(a[1]), "r"(a[2]), "r"(a[3]), "r"(b[0]), "r"(b[1]));
}
#define CP_COMMIT() asm volatile("cp.async.commit_group;" ::: "memory")
#define CP_WAIT1()  asm volatile("cp.async.wait_group 1;" ::: "memory")
#define CP_WAIT0()  asm volatile("cp.async.wait_group 0;" ::: "memory")

// ======================= Kernel: esq (exact, XLA order) ====================
__global__ void esq_kernel(const float* __restrict__ emb) {
    int warp = (blockIdx.x * blockDim.x + threadIdx.x) >> 5;
    int lane = threadIdx.x & 31;
    if (warp >= NEMB) return;
    const float* row = emb + (size_t)warp * KDIM;
    float s = 0.f;
#pragma unroll
    for (int c = lane; c < KDIM; c += 32) {
        float v = row[c];
        s = __fadd_rn(s, __fmul_rn(v, v));
    }
#pragma unroll
    for (int o = 16; o; o >>= 1)
        s = __fadd_rn(s, __shfl_xor_sync(0xffffffffu, s, o));
    if (lane == 0) g_esq[warp] = s;
}

// ======================= Kernel: convert emb -> bf16 hi/lo =================
__global__ void convB_kernel(const float* __restrict__ emb) {
    int i = (blockIdx.x * 256 + threadIdx.x) * 4;
    float4 v = *(const float4*)(emb + i);
    float vv[4] = {v.x, v.y, v.z, v.w};
    unsigned short hs[4], ls[4];
#pragma unroll
    for (int j = 0; j < 4; j++) {
        __nv_bfloat16 h = __float2bfloat16_rn(vv[j]);
        __nv_bfloat16 l = __float2bfloat16_rn(vv[j] - __bfloat162float(h));
        hs[j] = *(unsigned short*)&h;
        ls[j] = *(unsigned short*)&l;
    }
    uint2 ph = make_uint2((uint32_t)hs[0] | ((uint32_t)hs[1] << 16),
                          (uint32_t)hs[2] | ((uint32_t)hs[3] << 16));
    uint2 pl = make_uint2((uint32_t)ls[0] | ((uint32_t)ls[1] << 16),
                          (uint32_t)ls[2] | ((uint32_t)ls[3] << 16));
    *(uint2*)(g_Bh + i) = ph;
    *(uint2*)(g_Bl + i) = pl;
}

// ======================= Kernel: mma.sync GEMM + argmin ====================
__device__ __forceinline__ void issueB(uint32_t smem_base, int cc, int tid) {
#pragma unroll
    for (int j = 0; j < 8; j++) {
        int idx = tid + j * 256;          // 0..2047 16B granules
        int h = idx >> 10;                // 0 hi, 1 lo
        int n = (idx >> 5) & 31;          // row within chunk
        int c = idx & 31;                 // 16B chunk within row
        const char* src = (const char*)(h ? (const void*)g_Bl : (const void*)g_Bh)
                          + (size_t)(cc * 32 + n) * 512 + (size_t)c * 16;
        uint32_t dst = smem_base + SB + (uint32_t)((cc & 1) * 32768 + h * 16384
                     + n * 512 + ((c ^ (n & 7)) << 4));
        asm volatile("cp.async.cg.shared.global [%0], [%1], 16;" :: "r"(dst), "l"(src) : "memory");
    }
    CP_COMMIT();
}

__global__ __launch_bounds__(256, 1)
void mma_kernel(const float* __restrict__ z) {
    extern __shared__ char smem[];
    const uint32_t smem_base = smem_u32(smem);
    const int tid  = threadIdx.x;
    const int lane = tid & 31;
    const int wid  = tid >> 5;
    const int n0   = blockIdx.x * 128;
    const int b    = n0 >> 12;
    const int hw0  = n0 & 4095;
    const float* zbase = z + (size_t)b * B_STRIDE + hw0;

    float* esq_s  = (float*)(smem + SESQ);
    float* mg_best = (float*)(smem + MG_BEST);
    int*   mg_idx  = (int*)(smem + MG_IDX);
    int*   mg_cnt  = (int*)(smem + MG_CNT);
    float* mg_cd   = (float*)(smem + MG_CD);
    short* mg_ce   = (short*)(smem + MG_CE);

    // prefetch first two B chunks
    issueB(smem_base, 0, tid);
    issueB(smem_base, 1, tid);

    for (int i = tid; i < NEMB; i += 256) esq_s[i] = g_esq[i];

    // ---- convert A: z fp32 -> bf16 hi/lo, k-major swizzled smem ----
    // one thread = one 16B granule (8 tokens x 1 channel): 2 LDG.128 -> 2 STS.128
#pragma unroll
    for (int it = 0; it < 16; it++) {
        int g  = tid + it * 256;          // granule 0..4095
        int c  = g >> 4;                  // channel (k)
        int gt = g & 15;                  // token granule (8 tokens)
        const float* src = zbase + (size_t)c * CH_STRIDE + gt * 8;
        float4 v0 = *(const float4*)(src);
        float4 v1 = *(const float4*)(src + 4);
        float vv[8] = {v0.x, v0.y, v0.z, v0.w, v1.x, v1.y, v1.z, v1.w};
        uint32_t ph[4], pl[4];
#pragma unroll
        for (int j = 0; j < 4; j++) {
            __nv_bfloat16 h0 = __float2bfloat16_rn(vv[2*j]);
            __nv_bfloat16 l0 = __float2bfloat16_rn(vv[2*j] - __bfloat162float(h0));
            __nv_bfloat16 h1 = __float2bfloat16_rn(vv[2*j+1]);
            __nv_bfloat16 l1 = __float2bfloat16_rn(vv[2*j+1] - __bfloat162float(h1));
            ph[j] = (uint32_t)*(unsigned short*)&h0 | ((uint32_t)*(unsigned short*)&h1 << 16);
            pl[j] = (uint32_t)*(unsigned short*)&l0 | ((uint32_t)*(unsigned short*)&l1 << 16);
        }
        uint32_t off = (uint32_t)c * 256 + (uint32_t)((gt ^ (c & 7)) << 4);
        *(uint4*)(smem + SA_H + off) = *(uint4*)ph;
        *(uint4*)(smem + SA_L + off) = *(uint4*)pl;
    }

    // ---- per-lane ldmatrix address bases ----
    const int l7  = lane & 7;
    const int lt1 = (lane >> 3) & 1;
    const int lt2 = (lane >> 4) & 1;
    const int M0  = wid * 16;
    const uint32_t aoff = (uint32_t)(lt2 * 8 + l7) * 256
                        + (uint32_t)((((M0 >> 3) + lt1) ^ l7) << 4);
    const uint32_t addrAh = smem_base + SA_H + aoff;
    const uint32_t addrAl = smem_base + SA_L + aoff;

    const int tIG = lane & 3;

    float best[2] = {3.0e38f, 3.0e38f};
    int   bid[2]  = {0, 0};
    int   cn[2]   = {0, 0};
    int   ovf[2]  = {0, 0};

    __syncthreads();   // A + esq ready

    // ---- load ALL A fragments into registers (chunk-invariant) ----
    uint32_t Ah[16][4], Al[16][4];
#pragma unroll
    for (int kk = 0; kk < 16; kk++) {
        ldsm4t(Ah[kk], addrAh + (uint32_t)kk * 4096);
        ldsm4t(Al[kk], addrAl + (uint32_t)kk * 4096);
    }

    for (int ec = 0; ec < 32; ec++) {
        if (ec < 31) { CP_WAIT1(); } else { CP_WAIT0(); }
        __syncthreads();
        const uint32_t bufb = smem_base + SB + (uint32_t)((ec & 1) * 32768);
        const uint32_t brow0 = bufb + (uint32_t)((lt2 * 8 + l7) * 512);        // NG=0
        const uint32_t brow1 = bufb + (uint32_t)(((16 + lt2 * 8 + l7)) * 512); // NG=16

        float acc[4][4];
#pragma unroll
        for (int t = 0; t < 4; t++)
#pragma unroll
            for (int r = 0; r < 4; r++) acc[t][r] = 0.f;

#pragma unroll
        for (int kk = 0; kk < 16; kk++) {
            const uint32_t kchunk = (uint32_t)(kk * 2) + (uint32_t)lt1;
            const uint32_t sw = ((kchunk ^ (uint32_t)l7) << 4);
            uint32_t bh0[4], bh1[4], bl0[4], bl1[4];
            ldsm4(bh0, brow0 + sw);
            ldsm4(bh1, brow1 + sw);
            ldsm4(bl0, brow0 + 16384 + sw);
            ldsm4(bl1, brow1 + 16384 + sw);
            // pass 1: zh * eh
            mma16816(acc[0], Ah[kk], &bh0[0]);
            mma16816(acc[1], Ah[kk], &bh0[2]);
            mma16816(acc[2], Ah[kk], &bh1[0]);
            mma16816(acc[3], Ah[kk], &bh1[2]);
            // pass 2: zh * el
            mma16816(acc[0], Ah[kk], &bl0[0]);
            mma16816(acc[1], Ah[kk], &bl0[2]);
            mma16816(acc[2], Ah[kk], &bl1[0]);
            mma16816(acc[3], Ah[kk], &bl1[2]);
            // pass 3: zl * eh
            mma16816(acc[0], Al[kk], &bh0[0]);
            mma16816(acc[1], Al[kk], &bh0[2]);
            mma16816(acc[2], Al[kk], &bh1[0]);
            mma16816(acc[3], Al[kk], &bh1[2]);
        }

        // ---- fold into running argmin + candidate lists ----
#pragma unroll
        for (int t = 0; t < 4; t++) {
#pragma unroll
            for (int rr = 0; rr < 4; rr++) {
                int e = ec * 32 + t * 8 + (tIG << 1) + (rr & 1);
                int s = rr >> 1;
                float d = __fmaf_rn(-2.0f, acc[t][rr], esq_s[e]);
                if (d < best[s]) { best[s] = d; bid[s] = e; }
                if (d <= best[s] + EPS) {
                    int base = (tid * 2 + s) * 6;
                    if (cn[s] == 6) {              // compact
                        int k2 = 0;
#pragma unroll
                        for (int j = 0; j < 6; j++) {
                            float dv = mg_cd[base + j];
                            short ev = mg_ce[base + j];
                            if (dv <= best[s] + EPS) { mg_cd[base + k2] = dv; mg_ce[base + k2] = ev; k2++; }
                        }
                        cn[s] = k2;
                    }
                    if (cn[s] < 6) { mg_cd[base + cn[s]] = d; mg_ce[base + cn[s]] = (short)e; cn[s]++; }
                    else ovf[s] = 1;
                }
            }
        }
        __syncthreads();
        if (ec < 30) issueB(smem_base, ec + 2, tid);
    }

    // ---- publish per-lane state, merge 4 lanes per token ----
#pragma unroll
    for (int s = 0; s < 2; s++) {
        int slot = tid * 2 + s;
        mg_best[slot] = best[s];
        mg_idx[slot]  = bid[s];
        mg_cnt[slot]  = ovf[s] ? 255 : cn[s];
    }
    __syncthreads();

    if (tid < 128) {
        int t = tid;
        int w = t >> 4, g = t & 7, s = (t >> 3) & 1;
        int Lbase = w * 32 + g * 4;
        float gb = 3.0e38f; int gi = 0;
#pragma unroll
        for (int q = 0; q < 4; q++) {
            int slot = (Lbase + q) * 2 + s;
            float v = mg_best[slot]; int vi = mg_idx[slot];
            if (v < gb || (v == gb && vi < gi)) { gb = v; gi = vi; }
        }
        int cnt = 0, anyovf = 0;
        short list[NCAND];
#pragma unroll
        for (int q = 0; q < 4; q++) {
            int slot = (Lbase + q) * 2 + s;
            int cq = mg_cnt[slot];
            if (cq == 255) { anyovf = 1; continue; }
            for (int j = 0; j < cq; j++) {
                if (mg_cd[slot * 6 + j] <= gb + EPS) {
                    if (cnt < NCAND) list[cnt++] = mg_ce[slot * 6 + j];
                    else anyovf = 1;
                }
            }
        }
        int n = n0 + t;
        g_idx[n] = gi;
        if (anyovf) g_candN[n] = 255;
        else if (cnt >= 2) {
            g_candN[n] = (unsigned char)cnt;
            for (int j = 0; j < cnt; j++) g_cands[(size_t)n * NCAND + j] = list[j];
        } else g_candN[n] = 0;
    }
}

// ======================= Kernel: exact repair ==============================
__global__ void repair_kernel(const float* __restrict__ z, const float* __restrict__ emb) {
    int n = blockIdx.x * blockDim.x + threadIdx.x;
    if (n >= N_TOK) return;
    int cnt = g_candN[n];
    if (cnt == 0) return;
    int b = n >> 12, hw = n & 4095;
    const float* zb = z + (size_t)b * B_STRIDE + hw;
    // z_sq in XLA order (32 lane-partials, xor-tree association)
    float p[32];
#pragma unroll
    for (int i = 0; i < 32; i++) p[i] = 0.f;
#pragma unroll
    for (int c8 = 0; c8 < 8; c8++)
#pragma unroll
        for (int i = 0; i < 32; i++) {
            float v = zb[(size_t)(c8 * 32 + i) * CH_STRIDE];
            p[i] = __fadd_rn(p[i], __fmul_rn(v, v));
        }
#pragma unroll
    for (int off = 16; off; off >>= 1)
#pragma unroll
        for (int i = 0; i < 16; i++)
            if (i < off) p[i] = __fadd_rn(p[i], p[i + off]);
    float zsq = p[0];

    float m = 3.0e38f; int mi = 0;
    int ncand = (cnt == 255) ? NEMB : cnt;
    for (int j = 0; j < ncand; j++) {
        int e = (cnt == 255) ? j : (int)g_cands[(size_t)n * NCAND + j];
        const float* er = emb + (size_t)e * KDIM;
        float acc = 0.f;
#pragma unroll 8
        for (int c = 0; c < KDIM; c++)
            acc = __fmaf_rn(zb[(size_t)c * CH_STRIDE], er[c], acc);
        float A = __fadd_rn(zsq, g_esq[e]);
        float d = __fsub_rn(A, __fmul_rn(2.0f, acc));
        if (d < m || (d == m && e < mi)) { m = d; mi = e; }
    }
    g_idx[n] = mi;
}

// ======================= Kernel: gather/scatter ============================
__global__ __launch_bounds__(256)
void scatter_kernel(const float* __restrict__ emb, float* __restrict__ out,
                    float* __restrict__ out_idx, int write_idx) {
    const int tid = threadIdx.x;
    const int n0 = blockIdx.x * 128;
    const int b = n0 >> 12, hw0 = n0 & 4095;
    float* obase = out + (size_t)b * B_STRIDE + hw0;
    const int tok = tid & 127;
    const int half = tid >> 7;
    const int myidx = g_idx[n0 + tok];
    if (tid < 128 && write_idx) out_idx[n0 + tid] = (float)g_idx[n0 + tid];
    const float* erow = emb + (size_t)myidx * KDIM;
#pragma unroll 4
    for (int c = half; c < KDIM; c += 2)
        obase[(size_t)c * CH_STRIDE + tok] = erow[c];
}

// ---------------------------------------------------------------------------
extern "C" void kernel_launch(void* const* d_in, const int* in_sizes, int n_in,
                              void* d_out, int out_size) {
    const float* z   = (const float*)d_in[0];
    const float* emb = (const float*)d_in[1];
    float* out = (float*)d_out;

    const int zq_elems = 32 * 256 * 64 * 64;
    int write_idx = (out_size >= zq_elems + N_TOK) ? 1 : 0;

    cudaFuncSetAttribute(mma_kernel, cudaFuncAttributeMaxDynamicSharedMemorySize, SM_TOTAL);

    esq_kernel<<<128, 256>>>(emb);
    convB_kernel<<<256, 256>>>(emb);
    mma_kernel<<<N_TOK / 128, 256, SM_TOTAL>>>(z);
    repair_kernel<<<N_TOK / 256, 256>>>(z, emb);
    scatter_kernel<<<N_TOK / 128, 256>>>(emb, out, out + zq_elems, write_idx);
}